// round 6
// baseline (speedup 1.0000x reference)
#include <cuda_runtime.h>
#include <mma.h>
#include <math.h>

using namespace nvcuda;

#define NN   50000
#define NP   50048
#define EE   400000
#define EP   450000
#define CIN  128
#define HID  64
#define HEADS 8
#define HC   512
#define OUTD 3

// ---------------- scratch ----------------
__device__ float g_ln[NP * HC];
__device__ float g_hw[NP * HC];
__device__ float g_h[NN * HC];
__device__ float g_alsrc[NN * HEADS];
__device__ float g_aldst[NN * HEADS];
__device__ float g_sinv[NN * HEADS];
__device__ float g_alpha[EP * HEADS];   // CSR order
__device__ float g_res[NN * OUTD];
__device__ int   g_deg[NN];
__device__ int   g_rowptr[NN + 1];
__device__ int   g_cursor[NN];
__device__ int   g_csrc[EP];

// ---------------- helpers ----------------
__device__ __forceinline__ void cpAsync16(unsigned dst, const void* src, int srcBytes) {
    asm volatile("cp.async.ca.shared.global [%0], [%1], 16, %2;"
                 :: "r"(dst), "l"(src), "r"(srcBytes));
}

__device__ __forceinline__ float gelu(float v) {
    return 0.5f * v * (1.0f + erff(v * 0.70710678118654752f));
}

// ---------------- CSR build ----------------
__global__ void zero_deg_kernel(int* deg) {
    int i = blockIdx.x * blockDim.x + threadIdx.x;
    if (i < NN) deg[i] = 0;
}

__global__ void deg_kernel(const int* __restrict__ ei, int* deg) {
    int e = blockIdx.x * blockDim.x + threadIdx.x;
    if (e >= EP) return;
    int dst = (e < EE) ? ei[EE + e] : e - EE;
    atomicAdd(&deg[dst], 1);
}

__global__ void scan_kernel(const int* __restrict__ deg, int* rowptr, int* cursor) {
    const int T = 1024;
    const int CH = (NN + T - 1) / T;
    int t = threadIdx.x;
    int base = t * CH;
    int s = 0;
    for (int i = 0; i < CH; i++) {
        int j = base + i;
        if (j < NN) s += deg[j];
    }
    __shared__ int sh[T];
    sh[t] = s;
    __syncthreads();
    for (int o = 1; o < T; o <<= 1) {
        int v = (t >= o) ? sh[t - o] : 0;
        __syncthreads();
        sh[t] += v;
        __syncthreads();
    }
    int run = (t > 0) ? sh[t - 1] : 0;
    for (int i = 0; i < CH; i++) {
        int j = base + i;
        if (j < NN) { rowptr[j] = run; cursor[j] = run; run += deg[j]; }
    }
    if (t == T - 1) rowptr[NN] = run;
}

__global__ void scatter_kernel(const int* __restrict__ ei, int* cursor, int* csrc) {
    int e = blockIdx.x * blockDim.x + threadIdx.x;
    if (e >= EP) return;
    int src, dst;
    if (e < EE) { src = ei[e]; dst = ei[EE + e]; } else { src = dst = e - EE; }
    int pos = atomicAdd(&cursor[dst], 1);
    csrc[pos] = src;
}

// ---------------- LayerNorm (raw input x only) ----------------
__global__ void ln_kernel(const float* __restrict__ x, const float* __restrict__ g,
                          const float* __restrict__ b, float* __restrict__ out, int ci) {
    int n = blockIdx.x;
    const float* row = x + (size_t)n * ci;
    float s1 = 0.f, s2 = 0.f;
    for (int k = threadIdx.x; k < ci; k += 128) {
        float v = row[k];
        s1 += v; s2 += v * v;
    }
    __shared__ float sh1[4], sh2[4];
    for (int o = 16; o > 0; o >>= 1) {
        s1 += __shfl_down_sync(0xffffffffu, s1, o);
        s2 += __shfl_down_sync(0xffffffffu, s2, o);
    }
    int w = threadIdx.x >> 5, l = threadIdx.x & 31;
    if (l == 0) { sh1[w] = s1; sh2[w] = s2; }
    __syncthreads();
    if (threadIdx.x == 0) {
        float a = 0.f, c = 0.f;
        for (int i = 0; i < 4; i++) { a += sh1[i]; c += sh2[i]; }
        sh1[0] = a; sh2[0] = c;
    }
    __syncthreads();
    float inv = 1.0f / (float)ci;
    float mean = sh1[0] * inv;
    float var  = sh2[0] * inv - mean * mean;
    float rstd = rsqrtf(var + 1e-6f);
    float* orow = out + (size_t)n * ci;
    for (int k = threadIdx.x; k < ci; k += 128)
        orow[k] = (row[k] - mean) * rstd * g[k] + b[k];
}

// ---------------- tf32 GEMM, double-buffered, ONE sync per iter ----------------
#define BM 128
#define BN 128
#define BK 16
#define SPAD 8
#define SLD (BK + SPAD)

__global__ void gemm_tf32(const float* __restrict__ A, const float* __restrict__ B,
                          float* __restrict__ C, int M, int K, int Nc) {
    __shared__ __align__(16) float As[2][BM][SLD];
    __shared__ __align__(16) float Bs[2][BN][SLD];
    int tid = threadIdx.x;
    int warp = tid >> 5;
    int wm = warp >> 1;
    int wn = warp & 1;
    int rowBase = blockIdx.y * BM;
    int colBase = blockIdx.x * BN;

    int r = tid >> 2;
    int c = (tid & 3) * 4;

    wmma::fragment<wmma::accumulator, 16, 16, 8, float> acc[2][4];
    #pragma unroll
    for (int i = 0; i < 2; i++)
        #pragma unroll
        for (int j = 0; j < 4; j++) wmma::fill_fragment(acc[i][j], 0.f);

    int nIter = K / BK;

    auto loadStage = [&](int s, int it) {
        int k0 = it * BK;
        #pragma unroll
        for (int i = 0; i < 2; i++) {
            int rr = r + i * 64;
            int gr = rowBase + rr;
            unsigned da = (unsigned)__cvta_generic_to_shared(&As[s][rr][c]);
            cpAsync16(da, A + (size_t)gr * K + k0 + c, gr < M ? 16 : 0);
            unsigned db = (unsigned)__cvta_generic_to_shared(&Bs[s][rr][c]);
            cpAsync16(db, B + (size_t)(colBase + rr) * K + k0 + c, 16);
        }
        asm volatile("cp.async.commit_group;");
    };

    loadStage(0, 0);

    for (int it = 0; it < nIter; it++) {
        int buf = it & 1;
        // wait for load(it); everyone also done computing buf^1 from it-1
        asm volatile("cp.async.wait_group 0;");
        __syncthreads();
        if (it + 1 < nIter) loadStage(buf ^ 1, it + 1);  // overlaps compute below
        #pragma unroll
        for (int kk = 0; kk < BK; kk += 8) {
            wmma::fragment<wmma::matrix_a, 16, 16, 8, wmma::precision::tf32, wmma::row_major> af[2];
            wmma::fragment<wmma::matrix_b, 16, 16, 8, wmma::precision::tf32, wmma::col_major> bf[4];
            #pragma unroll
            for (int i = 0; i < 2; i++)
                wmma::load_matrix_sync(af[i], &As[buf][wm * 32 + i * 16][kk], SLD);
            #pragma unroll
            for (int j = 0; j < 4; j++)
                wmma::load_matrix_sync(bf[j], &Bs[buf][wn * 64 + j * 16][kk], SLD);
            #pragma unroll
            for (int i = 0; i < 2; i++)
                #pragma unroll
                for (int j = 0; j < 4; j++)
                    wmma::mma_sync(acc[i][j], af[i], bf[j], acc[i][j]);
        }
    }
    __syncthreads();
    #pragma unroll
    for (int i = 0; i < 2; i++)
        #pragma unroll
        for (int j = 0; j < 4; j++) {
            int rr = rowBase + wm * 32 + i * 16;
            int cc = colBase + wn * 64 + j * 16;
            wmma::store_matrix_sync(C + (size_t)rr * Nc + cc, acc[i][j], Nc, wmma::mem_row_major);
        }
}

// ---------------- attention logits: half-warp per (n,h), float4 loads ----------------
__global__ void attn_kernel(const float* __restrict__ hw, const float* __restrict__ asr,
                            const float* __restrict__ adt,
                            float* __restrict__ alsrc, float* __restrict__ aldst) {
    int item = blockIdx.x * 16 + (threadIdx.x >> 4);   // (n*8+h)
    if (item >= NN * HEADS) return;
    int l16 = threadIdx.x & 15;
    int h = item & 7;
    float4 v  = ((const float4*)(hw + (size_t)item * 64))[l16];
    float4 a1 = ((const float4*)(asr + h * 64))[l16];
    float4 a2 = ((const float4*)(adt + h * 64))[l16];
    float s1 = v.x * a1.x + v.y * a1.y + v.z * a1.z + v.w * a1.w;
    float s2 = v.x * a2.x + v.y * a2.y + v.z * a2.z + v.w * a2.w;
    #pragma unroll
    for (int o = 8; o > 0; o >>= 1) {
        s1 += __shfl_xor_sync(0xffffffffu, s1, o);
        s2 += __shfl_xor_sync(0xffffffffu, s2, o);
    }
    if (l16 == 0) { alsrc[item] = s1; aldst[item] = s2; }
}

// ---------------- gather softmax (H=8): one thread per dst, all heads ----------------
__global__ void soft8_kernel(const int* __restrict__ rp, const int* __restrict__ csrc,
                             const float* __restrict__ alsrc, const float* __restrict__ aldst,
                             float* __restrict__ alpha, float* __restrict__ sinv) {
    int dst = blockIdx.x * blockDim.x + threadIdx.x;
    if (dst >= NN) return;
    int s0 = rp[dst], s1 = rp[dst + 1];
    float4 ad0 = *(const float4*)(aldst + dst * 8);
    float4 ad1 = *(const float4*)(aldst + dst * 8 + 4);
    float sum[8] = {0.f, 0.f, 0.f, 0.f, 0.f, 0.f, 0.f, 0.f};
    for (int i = s0; i < s1; i++) {
        int src = __ldg(&csrc[i]);
        float4 v0 = *(const float4*)(alsrc + src * 8);
        float4 v1 = *(const float4*)(alsrc + src * 8 + 4);
        float e[8];
        e[0] = v0.x + ad0.x; e[1] = v0.y + ad0.y; e[2] = v0.z + ad0.z; e[3] = v0.w + ad0.w;
        e[4] = v1.x + ad1.x; e[5] = v1.y + ad1.y; e[6] = v1.z + ad1.z; e[7] = v1.w + ad1.w;
        #pragma unroll
        for (int k = 0; k < 8; k++) {
            float t = e[k] > 0.f ? e[k] : 0.2f * e[k];
            e[k] = expf(t);
            sum[k] += e[k];
        }
        *(float4*)(alpha + (size_t)i * 8)     = make_float4(e[0], e[1], e[2], e[3]);
        *(float4*)(alpha + (size_t)i * 8 + 4) = make_float4(e[4], e[5], e[6], e[7]);
    }
    float4 r0, r1;
    r0.x = __frcp_rn(sum[0]); r0.y = __frcp_rn(sum[1]); r0.z = __frcp_rn(sum[2]); r0.w = __frcp_rn(sum[3]);
    r1.x = __frcp_rn(sum[4]); r1.y = __frcp_rn(sum[5]); r1.z = __frcp_rn(sum[6]); r1.w = __frcp_rn(sum[7]);
    *(float4*)(sinv + dst * 8)     = r0;
    *(float4*)(sinv + dst * 8 + 4) = r1;
}

// ---------------- gather softmax (H=1) ----------------
__global__ void soft1_kernel(const int* __restrict__ rp, const int* __restrict__ csrc,
                             const float* __restrict__ alsrc, const float* __restrict__ aldst,
                             float* __restrict__ alpha, float* __restrict__ sinv) {
    int dst = blockIdx.x * blockDim.x + threadIdx.x;
    if (dst >= NN) return;
    int s0 = rp[dst], s1 = rp[dst + 1];
    float ad = aldst[dst];
    float sum = 0.f;
    for (int i = s0; i < s1; i++) {
        int src = __ldg(&csrc[i]);
        float v = __ldg(&alsrc[src]) + ad;
        v = v > 0.f ? v : 0.2f * v;
        float ex = expf(v);
        alpha[i] = ex;
        sum += ex;
    }
    sinv[dst] = __frcp_rn(sum);
}

// ---------------- fused gather: agg + bias + gelu + residual + next-LN ----------------
__global__ void msgB_kernel(const int* __restrict__ rp, const int* __restrict__ csrc,
                            const float* __restrict__ alpha, const float* __restrict__ sinv,
                            const float* __restrict__ hw, const float* __restrict__ bias,
                            const float* __restrict__ lg, const float* __restrict__ lb,
                            float* __restrict__ h, float* __restrict__ lnout, int addRes) {
    int dst = blockIdx.x;
    int tid = threadIdx.x;
    int hh = tid >> 4;
    int s0 = rp[dst], s1 = rp[dst + 1];
    float siv = sinv[dst * 8 + hh];
    float4 acc = make_float4(0.f, 0.f, 0.f, 0.f);
    int i = s0;
    // unrolled-by-2: two independent gathers in flight
    for (; i + 1 < s1; i += 2) {
        int srcA = __ldg(&csrc[i]);
        int srcB = __ldg(&csrc[i + 1]);
        float aA = __ldg(&alpha[(size_t)i * 8 + hh]);
        float aB = __ldg(&alpha[(size_t)(i + 1) * 8 + hh]);
        float4 vA = *(const float4*)(hw + ((size_t)srcA << 9) + (tid << 2));
        float4 vB = *(const float4*)(hw + ((size_t)srcB << 9) + (tid << 2));
        acc.x += aA * vA.x + aB * vB.x;
        acc.y += aA * vA.y + aB * vB.y;
        acc.z += aA * vA.z + aB * vB.z;
        acc.w += aA * vA.w + aB * vB.w;
    }
    if (i < s1) {
        int src = __ldg(&csrc[i]);
        float a = __ldg(&alpha[(size_t)i * 8 + hh]);
        float4 v = *(const float4*)(hw + ((size_t)src << 9) + (tid << 2));
        acc.x += a * v.x; acc.y += a * v.y; acc.z += a * v.z; acc.w += a * v.w;
    }
    acc.x *= siv; acc.y *= siv; acc.z *= siv; acc.w *= siv;
    float4 bb = *(const float4*)(bias + (tid << 2));
    float4 r;
    r.x = gelu(acc.x + bb.x);
    r.y = gelu(acc.y + bb.y);
    r.z = gelu(acc.z + bb.z);
    r.w = gelu(acc.w + bb.w);
    float* hrow = h + ((size_t)dst << 9) + (tid << 2);
    if (addRes) {
        float4 old = *(const float4*)hrow;
        r.x += old.x; r.y += old.y; r.z += old.z; r.w += old.w;
    }
    *(float4*)hrow = r;

    float p1 = r.x + r.y + r.z + r.w;
    float p2 = r.x * r.x + r.y * r.y + r.z * r.z + r.w * r.w;
    __shared__ float sh1[4], sh2[4];
    for (int o = 16; o > 0; o >>= 1) {
        p1 += __shfl_down_sync(0xffffffffu, p1, o);
        p2 += __shfl_down_sync(0xffffffffu, p2, o);
    }
    int w = tid >> 5, l = tid & 31;
    if (l == 0) { sh1[w] = p1; sh2[w] = p2; }
    __syncthreads();
    if (tid == 0) {
        sh1[0] = sh1[0] + sh1[1] + sh1[2] + sh1[3];
        sh2[0] = sh2[0] + sh2[1] + sh2[2] + sh2[3];
    }
    __syncthreads();
    float mean = sh1[0] * (1.0f / 512.0f);
    float var  = sh2[0] * (1.0f / 512.0f) - mean * mean;
    float rstd = rsqrtf(var + 1e-6f);
    float4 gg = *(const float4*)(lg + (tid << 2));
    float4 bv = *(const float4*)(lb + (tid << 2));
    float4 o4;
    o4.x = (r.x - mean) * rstd * gg.x + bv.x;
    o4.y = (r.y - mean) * rstd * gg.y + bv.y;
    o4.z = (r.z - mean) * rstd * gg.z + bv.z;
    o4.w = (r.w - mean) * rstd * gg.w + bv.w;
    *(float4*)(lnout + ((size_t)dst << 9) + (tid << 2)) = o4;
}

// ---------------- layer 3 tiny GEMM + logits ----------------
__global__ void gemm3_kernel(const float* __restrict__ ln, const float* __restrict__ W,
                             const float* __restrict__ asr, const float* __restrict__ adt,
                             float* hw3, float* alsrc, float* aldst) {
    int n = blockIdx.x, t = threadIdx.x;
    const float* row = ln + (size_t)n * 512;
    float p0 = 0.f, p1 = 0.f, p2 = 0.f;
    for (int k = t; k < 512; k += 128) {
        float a = row[k];
        p0 += a * W[k];
        p1 += a * W[512 + k];
        p2 += a * W[1024 + k];
    }
    __shared__ float sh[3][4];
    for (int o = 16; o > 0; o >>= 1) {
        p0 += __shfl_down_sync(0xffffffffu, p0, o);
        p1 += __shfl_down_sync(0xffffffffu, p1, o);
        p2 += __shfl_down_sync(0xffffffffu, p2, o);
    }
    int w = t >> 5, l = t & 31;
    if (l == 0) { sh[0][w] = p0; sh[1][w] = p1; sh[2][w] = p2; }
    __syncthreads();
    if (t == 0) {
        float v0 = sh[0][0] + sh[0][1] + sh[0][2] + sh[0][3];
        float v1 = sh[1][0] + sh[1][1] + sh[1][2] + sh[1][3];
        float v2 = sh[2][0] + sh[2][1] + sh[2][2] + sh[2][3];
        hw3[n * 3 + 0] = v0; hw3[n * 3 + 1] = v1; hw3[n * 3 + 2] = v2;
        alsrc[n] = v0 * asr[0] + v1 * asr[1] + v2 * asr[2];
        aldst[n] = v0 * adt[0] + v1 * adt[1] + v2 * adt[2];
    }
}

// ---------------- final gather ----------------
__global__ void final_gather(const int* __restrict__ rp, const int* __restrict__ csrc,
                             const float* __restrict__ alpha, const float* __restrict__ sinv,
                             const float* __restrict__ hw3, const float* __restrict__ b3,
                             const float* __restrict__ res, float* __restrict__ out) {
    int dst = blockIdx.x * blockDim.x + threadIdx.x;
    if (dst >= NN) return;
    int s0 = rp[dst], s1 = rp[dst + 1];
    float siv = sinv[dst];
    float a0 = 0.f, a1 = 0.f, a2 = 0.f;
    for (int i = s0; i < s1; i++) {
        int src = __ldg(&csrc[i]);
        float a = __ldg(&alpha[i]) * siv;
        a0 += a * __ldg(&hw3[src * 3 + 0]);
        a1 += a * __ldg(&hw3[src * 3 + 1]);
        a2 += a * __ldg(&hw3[src * 3 + 2]);
    }
    out[dst * 3 + 0] = a0 + b3[0] + res[dst * 3 + 0];
    out[dst * 3 + 1] = a1 + b3[1] + res[dst * 3 + 1];
    out[dst * 3 + 2] = a2 + b3[2] + res[dst * 3 + 2];
}

// ---------------- input residual ----------------
__global__ void resid_kernel(const float* __restrict__ x, const float* __restrict__ rw,
                             const float* __restrict__ rb, float* res) {
    int n = blockIdx.x, t = threadIdx.x;
    float a = x[(size_t)n * 128 + t];
    float p0 = a * rw[t], p1 = a * rw[128 + t], p2 = a * rw[256 + t];
    __shared__ float sh[3][4];
    for (int o = 16; o > 0; o >>= 1) {
        p0 += __shfl_down_sync(0xffffffffu, p0, o);
        p1 += __shfl_down_sync(0xffffffffu, p1, o);
        p2 += __shfl_down_sync(0xffffffffu, p2, o);
    }
    int w = t >> 5, l = t & 31;
    if (l == 0) { sh[0][w] = p0; sh[1][w] = p1; sh[2][w] = p2; }
    __syncthreads();
    if (t == 0) {
        res[n * 3 + 0] = sh[0][0] + sh[0][1] + sh[0][2] + sh[0][3] + rb[0];
        res[n * 3 + 1] = sh[1][0] + sh[1][1] + sh[1][2] + sh[1][3] + rb[1];
        res[n * 3 + 2] = sh[2][0] + sh[2][1] + sh[2][2] + sh[2][3] + rb[2];
    }
}

// ---------------- launch ----------------
extern "C" void kernel_launch(void* const* d_in, const int* in_sizes, int n_in,
                              void* d_out, int out_size) {
    const float* x    = (const float*)d_in[0];
    const int*   ei   = (const int*)d_in[1];
    const float* resW = (const float*)d_in[2];
    const float* resb = (const float*)d_in[3];

    const float* lng[4];  const float* lnb[4];
    const float* Wl[4];   const float* asr[4];
    const float* adt[4];  const float* bl[4];
    for (int l = 0; l < 4; l++) {
        int base = 4 + 6 * l;
        lng[l] = (const float*)d_in[base + 0];
        lnb[l] = (const float*)d_in[base + 1];
        Wl[l]  = (const float*)d_in[base + 2];
        asr[l] = (const float*)d_in[base + 3];
        adt[l] = (const float*)d_in[base + 4];
        bl[l]  = (const float*)d_in[base + 5];
    }

    float *ln_, *hw_, *h_, *alsrc_, *aldst_, *sinv_, *alpha_, *res_;
    int *deg_, *rp_, *cur_, *csrc_;
    cudaGetSymbolAddress((void**)&ln_,    g_ln);
    cudaGetSymbolAddress((void**)&hw_,    g_hw);
    cudaGetSymbolAddress((void**)&h_,     g_h);
    cudaGetSymbolAddress((void**)&alsrc_, g_alsrc);
    cudaGetSymbolAddress((void**)&aldst_, g_aldst);
    cudaGetSymbolAddress((void**)&sinv_,  g_sinv);
    cudaGetSymbolAddress((void**)&alpha_, g_alpha);
    cudaGetSymbolAddress((void**)&res_,   g_res);
    cudaGetSymbolAddress((void**)&deg_,   g_deg);
    cudaGetSymbolAddress((void**)&rp_,    g_rowptr);
    cudaGetSymbolAddress((void**)&cur_,   g_cursor);
    cudaGetSymbolAddress((void**)&csrc_,  g_csrc);

    zero_deg_kernel<<<(NN + 255) / 256, 256>>>(deg_);
    deg_kernel<<<(EP + 255) / 256, 256>>>(ei, deg_);
    scan_kernel<<<1, 1024>>>(deg_, rp_, cur_);
    scatter_kernel<<<(EP + 255) / 256, 256>>>(ei, cur_, csrc_);

    resid_kernel<<<NN, 128>>>(x, resW, resb, res_);
    ln_kernel<<<NN, 128>>>(x, lng[0], lnb[0], ln_, CIN);

    for (int l = 0; l < 3; l++) {
        int ci = (l == 0) ? CIN : HC;
        gemm_tf32<<<dim3(HC / BN, NP / BM), 256>>>(ln_, Wl[l], hw_, NN, ci, HC);
        attn_kernel<<<(NN * HEADS + 15) / 16, 256>>>(hw_, asr[l], adt[l], alsrc_, aldst_);
        soft8_kernel<<<(NN + 255) / 256, 256>>>(rp_, csrc_, alsrc_, aldst_, alpha_, sinv_);
        msgB_kernel<<<NN, 128>>>(rp_, csrc_, alpha_, sinv_, hw_, bl[l],
                                 lng[l + 1], lnb[l + 1], h_, ln_, l > 0 ? 1 : 0);
    }

    gemm3_kernel<<<NN, 128>>>(ln_, Wl[3], asr[3], adt[3], hw_, alsrc_, aldst_);
    soft1_kernel<<<(NN + 255) / 256, 256>>>(rp_, csrc_, alsrc_, aldst_, alpha_, sinv_);
    final_gather<<<(NN + 255) / 256, 256>>>(rp_, csrc_, alpha_, sinv_, hw_, bl[3], res_, (float*)d_out);
}

// round 7
// speedup vs baseline: 1.4404x; 1.4404x over previous
#include <cuda_runtime.h>
#include <mma.h>
#include <math.h>

using namespace nvcuda;

#define NN   50000
#define NP   50048
#define EE   400000
#define EP   450000
#define CIN  128
#define HID  64
#define HEADS 8
#define HC   512
#define OUTD 3

// ---------------- scratch ----------------
__device__ float g_ln[NP * HC];
__device__ float g_hw[NP * HC];
__device__ float g_h[NN * HC];
__device__ float g_alsrc[NN * HEADS];
__device__ float g_aldst[NN * HEADS];
__device__ float g_sinv[NN * HEADS];
__device__ float g_alpha[EP * HEADS];   // CSR order
__device__ float g_res[NN * OUTD];
__device__ int   g_deg[NN];
__device__ int   g_rowptr[NN + 1];
__device__ int   g_cursor[NN];
__device__ int   g_csrc[EP];

// ---------------- helpers ----------------
__device__ __forceinline__ void cpAsync16(unsigned dst, const void* src, int srcBytes) {
    asm volatile("cp.async.ca.shared.global [%0], [%1], 16, %2;"
                 :: "r"(dst), "l"(src), "r"(srcBytes));
}

__device__ __forceinline__ float gelu(float v) {
    return 0.5f * v * (1.0f + erff(v * 0.70710678118654752f));
}

// ---------------- CSR build ----------------
__global__ void zero_deg_kernel(int* deg) {
    int i = blockIdx.x * blockDim.x + threadIdx.x;
    if (i < NN) deg[i] = 0;
}

__global__ void deg_kernel(const int* __restrict__ ei, int* deg) {
    int e = blockIdx.x * blockDim.x + threadIdx.x;
    if (e >= EP) return;
    int dst = (e < EE) ? ei[EE + e] : e - EE;
    atomicAdd(&deg[dst], 1);
}

__global__ void scan_kernel(const int* __restrict__ deg, int* rowptr, int* cursor) {
    const int T = 1024;
    const int CH = (NN + T - 1) / T;
    int t = threadIdx.x;
    int base = t * CH;
    int s = 0;
    for (int i = 0; i < CH; i++) {
        int j = base + i;
        if (j < NN) s += deg[j];
    }
    __shared__ int sh[T];
    sh[t] = s;
    __syncthreads();
    for (int o = 1; o < T; o <<= 1) {
        int v = (t >= o) ? sh[t - o] : 0;
        __syncthreads();
        sh[t] += v;
        __syncthreads();
    }
    int run = (t > 0) ? sh[t - 1] : 0;
    for (int i = 0; i < CH; i++) {
        int j = base + i;
        if (j < NN) { rowptr[j] = run; cursor[j] = run; run += deg[j]; }
    }
    if (t == T - 1) rowptr[NN] = run;
}

__global__ void scatter_kernel(const int* __restrict__ ei, int* cursor, int* csrc) {
    int e = blockIdx.x * blockDim.x + threadIdx.x;
    if (e >= EP) return;
    int src, dst;
    if (e < EE) { src = ei[e]; dst = ei[EE + e]; } else { src = dst = e - EE; }
    int pos = atomicAdd(&cursor[dst], 1);
    csrc[pos] = src;
}

// ---------------- LayerNorm (raw input x only) ----------------
__global__ void ln_kernel(const float* __restrict__ x, const float* __restrict__ g,
                          const float* __restrict__ b, float* __restrict__ out, int ci) {
    int n = blockIdx.x;
    const float* row = x + (size_t)n * ci;
    float s1 = 0.f, s2 = 0.f;
    for (int k = threadIdx.x; k < ci; k += 128) {
        float v = row[k];
        s1 += v; s2 += v * v;
    }
    __shared__ float sh1[4], sh2[4];
    for (int o = 16; o > 0; o >>= 1) {
        s1 += __shfl_down_sync(0xffffffffu, s1, o);
        s2 += __shfl_down_sync(0xffffffffu, s2, o);
    }
    int w = threadIdx.x >> 5, l = threadIdx.x & 31;
    if (l == 0) { sh1[w] = s1; sh2[w] = s2; }
    __syncthreads();
    if (threadIdx.x == 0) {
        float a = 0.f, c = 0.f;
        for (int i = 0; i < 4; i++) { a += sh1[i]; c += sh2[i]; }
        sh1[0] = a; sh2[0] = c;
    }
    __syncthreads();
    float inv = 1.0f / (float)ci;
    float mean = sh1[0] * inv;
    float var  = sh2[0] * inv - mean * mean;
    float rstd = rsqrtf(var + 1e-6f);
    float* orow = out + (size_t)n * ci;
    for (int k = threadIdx.x; k < ci; k += 128)
        orow[k] = (row[k] - mean) * rstd * g[k] + b[k];
}

// ---------------- tf32 GEMM, 3-stage cp.async pipeline (R5 wait pattern) ----------------
#define BM 128
#define BN 128
#define BK 16
#define SPAD 8
#define SLD (BK + SPAD)

__global__ void gemm_tf32(const float* __restrict__ A, const float* __restrict__ B,
                          float* __restrict__ C, int M, int K, int Nc) {
    __shared__ __align__(16) float As[3][BM][SLD];
    __shared__ __align__(16) float Bs[3][BN][SLD];
    int tid = threadIdx.x;
    int warp = tid >> 5;
    int wm = warp >> 1;
    int wn = warp & 1;
    int rowBase = blockIdx.y * BM;
    int colBase = blockIdx.x * BN;

    int r = tid >> 2;
    int c = (tid & 3) * 4;

    wmma::fragment<wmma::accumulator, 16, 16, 8, float> acc[2][4];
    #pragma unroll
    for (int i = 0; i < 2; i++)
        #pragma unroll
        for (int j = 0; j < 4; j++) wmma::fill_fragment(acc[i][j], 0.f);

    int nIter = K / BK;

    auto loadStage = [&](int s, int it) {
        int k0 = it * BK;
        #pragma unroll
        for (int i = 0; i < 2; i++) {
            int rr = r + i * 64;
            int gr = rowBase + rr;
            unsigned da = (unsigned)__cvta_generic_to_shared(&As[s][rr][c]);
            cpAsync16(da, A + (size_t)gr * K + k0 + c, gr < M ? 16 : 0);
            unsigned db = (unsigned)__cvta_generic_to_shared(&Bs[s][rr][c]);
            cpAsync16(db, B + (size_t)(colBase + rr) * K + k0 + c, 16);
        }
        asm volatile("cp.async.commit_group;");
    };

    loadStage(0, 0);
    if (nIter > 1) loadStage(1, 1);

    int buf = 0;
    for (int it = 0; it < nIter; it++) {
        if (it + 2 < nIter) {
            loadStage((buf + 2) % 3, it + 2);   // keep two loads in flight
            asm volatile("cp.async.wait_group 2;");
        } else if (it + 1 < nIter) {
            asm volatile("cp.async.wait_group 1;");
        } else {
            asm volatile("cp.async.wait_group 0;");
        }
        __syncthreads();
        #pragma unroll
        for (int kk = 0; kk < BK; kk += 8) {
            wmma::fragment<wmma::matrix_a, 16, 16, 8, wmma::precision::tf32, wmma::row_major> af[2];
            wmma::fragment<wmma::matrix_b, 16, 16, 8, wmma::precision::tf32, wmma::col_major> bf[4];
            #pragma unroll
            for (int i = 0; i < 2; i++)
                wmma::load_matrix_sync(af[i], &As[buf][wm * 32 + i * 16][kk], SLD);
            #pragma unroll
            for (int j = 0; j < 4; j++)
                wmma::load_matrix_sync(bf[j], &Bs[buf][wn * 64 + j * 16][kk], SLD);
            #pragma unroll
            for (int i = 0; i < 2; i++)
                #pragma unroll
                for (int j = 0; j < 4; j++)
                    wmma::mma_sync(acc[i][j], af[i], bf[j], acc[i][j]);
        }
        __syncthreads();
        buf = (buf + 1) % 3;
    }
    #pragma unroll
    for (int i = 0; i < 2; i++)
        #pragma unroll
        for (int j = 0; j < 4; j++) {
            int rr = rowBase + wm * 32 + i * 16;
            int cc = colBase + wn * 64 + j * 16;
            wmma::store_matrix_sync(C + (size_t)rr * Nc + cc, acc[i][j], Nc, wmma::mem_row_major);
        }
}

// ---------------- attention logits: one warp per (n,h) (R5 form) ----------------
__global__ void attn_kernel(const float* __restrict__ hw, const float* __restrict__ asr,
                            const float* __restrict__ adt,
                            float* __restrict__ alsrc, float* __restrict__ aldst) {
    int item = blockIdx.x * 8 + (threadIdx.x >> 5);
    if (item >= NN * HEADS) return;
    int lane = threadIdx.x & 31;
    int h = item & (HEADS - 1);
    const float2* v  = (const float2*)(hw + (size_t)item * 64);
    const float2* w1 = (const float2*)(asr + h * 64);
    const float2* w2 = (const float2*)(adt + h * 64);
    float2 vv = v[lane], a1 = w1[lane], a2 = w2[lane];
    float s1 = vv.x * a1.x + vv.y * a1.y;
    float s2 = vv.x * a2.x + vv.y * a2.y;
    for (int o = 16; o > 0; o >>= 1) {
        s1 += __shfl_xor_sync(0xffffffffu, s1, o);
        s2 += __shfl_xor_sync(0xffffffffu, s2, o);
    }
    if (lane == 0) { alsrc[item] = s1; aldst[item] = s2; }
}

// ---------------- gather softmax (H=8): one thread per (dst, h) (R5 form) ----------------
__global__ void soft8_kernel(const int* __restrict__ rp, const int* __restrict__ csrc,
                             const float* __restrict__ alsrc, const float* __restrict__ aldst,
                             float* __restrict__ alpha, float* __restrict__ sinv) {
    int idx = blockIdx.x * blockDim.x + threadIdx.x;
    if (idx >= NN * HEADS) return;
    int dst = idx >> 3, h = idx & 7;
    int s0 = rp[dst], s1 = rp[dst + 1];
    float ad = aldst[idx];
    float sum = 0.f;
    for (int i = s0; i < s1; i++) {
        int src = __ldg(&csrc[i]);
        float v = __ldg(&alsrc[src * 8 + h]) + ad;
        v = v > 0.f ? v : 0.2f * v;
        float ex = expf(v);
        alpha[(size_t)i * 8 + h] = ex;
        sum += ex;
    }
    sinv[idx] = __frcp_rn(sum);
}

// ---------------- gather softmax (H=1) ----------------
__global__ void soft1_kernel(const int* __restrict__ rp, const int* __restrict__ csrc,
                             const float* __restrict__ alsrc, const float* __restrict__ aldst,
                             float* __restrict__ alpha, float* __restrict__ sinv) {
    int dst = blockIdx.x * blockDim.x + threadIdx.x;
    if (dst >= NN) return;
    int s0 = rp[dst], s1 = rp[dst + 1];
    float ad = aldst[dst];
    float sum = 0.f;
    for (int i = s0; i < s1; i++) {
        int src = __ldg(&csrc[i]);
        float v = __ldg(&alsrc[src]) + ad;
        v = v > 0.f ? v : 0.2f * v;
        float ex = expf(v);
        alpha[i] = ex;
        sum += ex;
    }
    sinv[dst] = __frcp_rn(sum);
}

// ---------------- fused gather: agg + bias + gelu + residual + next-LN ----------------
__global__ void msgB_kernel(const int* __restrict__ rp, const int* __restrict__ csrc,
                            const float* __restrict__ alpha, const float* __restrict__ sinv,
                            const float* __restrict__ hw, const float* __restrict__ bias,
                            const float* __restrict__ lg, const float* __restrict__ lb,
                            float* __restrict__ h, float* __restrict__ lnout, int addRes) {
    int dst = blockIdx.x;
    int tid = threadIdx.x;
    int hh = tid >> 4;
    int s0 = rp[dst], s1 = rp[dst + 1];
    float siv = sinv[dst * 8 + hh];
    float4 acc = make_float4(0.f, 0.f, 0.f, 0.f);
    int i = s0;
    for (; i + 1 < s1; i += 2) {
        int srcA = __ldg(&csrc[i]);
        int srcB = __ldg(&csrc[i + 1]);
        float aA = __ldg(&alpha[(size_t)i * 8 + hh]);
        float aB = __ldg(&alpha[(size_t)(i + 1) * 8 + hh]);
        float4 vA = *(const float4*)(hw + ((size_t)srcA << 9) + (tid << 2));
        float4 vB = *(const float4*)(hw + ((size_t)srcB << 9) + (tid << 2));
        acc.x += aA * vA.x + aB * vB.x;
        acc.y += aA * vA.y + aB * vB.y;
        acc.z += aA * vA.z + aB * vB.z;
        acc.w += aA * vA.w + aB * vB.w;
    }
    if (i < s1) {
        int src = __ldg(&csrc[i]);
        float a = __ldg(&alpha[(size_t)i * 8 + hh]);
        float4 v = *(const float4*)(hw + ((size_t)src << 9) + (tid << 2));
        acc.x += a * v.x; acc.y += a * v.y; acc.z += a * v.z; acc.w += a * v.w;
    }
    acc.x *= siv; acc.y *= siv; acc.z *= siv; acc.w *= siv;
    float4 bb = *(const float4*)(bias + (tid << 2));
    float4 r;
    r.x = gelu(acc.x + bb.x);
    r.y = gelu(acc.y + bb.y);
    r.z = gelu(acc.z + bb.z);
    r.w = gelu(acc.w + bb.w);
    float* hrow = h + ((size_t)dst << 9) + (tid << 2);
    if (addRes) {
        float4 old = *(const float4*)hrow;
        r.x += old.x; r.y += old.y; r.z += old.z; r.w += old.w;
    }
    *(float4*)hrow = r;

    float p1 = r.x + r.y + r.z + r.w;
    float p2 = r.x * r.x + r.y * r.y + r.z * r.z + r.w * r.w;
    __shared__ float sh1[4], sh2[4];
    for (int o = 16; o > 0; o >>= 1) {
        p1 += __shfl_down_sync(0xffffffffu, p1, o);
        p2 += __shfl_down_sync(0xffffffffu, p2, o);
    }
    int w = tid >> 5, l = tid & 31;
    if (l == 0) { sh1[w] = p1; sh2[w] = p2; }
    __syncthreads();
    if (tid == 0) {
        sh1[0] = sh1[0] + sh1[1] + sh1[2] + sh1[3];
        sh2[0] = sh2[0] + sh2[1] + sh2[2] + sh2[3];
    }
    __syncthreads();
    float mean = sh1[0] * (1.0f / 512.0f);
    float var  = sh2[0] * (1.0f / 512.0f) - mean * mean;
    float rstd = rsqrtf(var + 1e-6f);
    float4 gg = *(const float4*)(lg + (tid << 2));
    float4 bv = *(const float4*)(lb + (tid << 2));
    float4 o4;
    o4.x = (r.x - mean) * rstd * gg.x + bv.x;
    o4.y = (r.y - mean) * rstd * gg.y + bv.y;
    o4.z = (r.z - mean) * rstd * gg.z + bv.z;
    o4.w = (r.w - mean) * rstd * gg.w + bv.w;
    *(float4*)(lnout + ((size_t)dst << 9) + (tid << 2)) = o4;
}

// ---------------- layer 3 tiny GEMM + logits ----------------
__global__ void gemm3_kernel(const float* __restrict__ ln, const float* __restrict__ W,
                             const float* __restrict__ asr, const float* __restrict__ adt,
                             float* hw3, float* alsrc, float* aldst) {
    int n = blockIdx.x, t = threadIdx.x;
    const float* row = ln + (size_t)n * 512;
    float p0 = 0.f, p1 = 0.f, p2 = 0.f;
    for (int k = t; k < 512; k += 128) {
        float a = row[k];
        p0 += a * W[k];
        p1 += a * W[512 + k];
        p2 += a * W[1024 + k];
    }
    __shared__ float sh[3][4];
    for (int o = 16; o > 0; o >>= 1) {
        p0 += __shfl_down_sync(0xffffffffu, p0, o);
        p1 += __shfl_down_sync(0xffffffffu, p1, o);
        p2 += __shfl_down_sync(0xffffffffu, p2, o);
    }
    int w = t >> 5, l = t & 31;
    if (l == 0) { sh[0][w] = p0; sh[1][w] = p1; sh[2][w] = p2; }
    __syncthreads();
    if (t == 0) {
        float v0 = sh[0][0] + sh[0][1] + sh[0][2] + sh[0][3];
        float v1 = sh[1][0] + sh[1][1] + sh[1][2] + sh[1][3];
        float v2 = sh[2][0] + sh[2][1] + sh[2][2] + sh[2][3];
        hw3[n * 3 + 0] = v0; hw3[n * 3 + 1] = v1; hw3[n * 3 + 2] = v2;
        alsrc[n] = v0 * asr[0] + v1 * asr[1] + v2 * asr[2];
        aldst[n] = v0 * adt[0] + v1 * adt[1] + v2 * adt[2];
    }
}

// ---------------- final gather ----------------
__global__ void final_gather(const int* __restrict__ rp, const int* __restrict__ csrc,
                             const float* __restrict__ alpha, const float* __restrict__ sinv,
                             const float* __restrict__ hw3, const float* __restrict__ b3,
                             const float* __restrict__ res, float* __restrict__ out) {
    int dst = blockIdx.x * blockDim.x + threadIdx.x;
    if (dst >= NN) return;
    int s0 = rp[dst], s1 = rp[dst + 1];
    float siv = sinv[dst];
    float a0 = 0.f, a1 = 0.f, a2 = 0.f;
    for (int i = s0; i < s1; i++) {
        int src = __ldg(&csrc[i]);
        float a = __ldg(&alpha[i]) * siv;
        a0 += a * __ldg(&hw3[src * 3 + 0]);
        a1 += a * __ldg(&hw3[src * 3 + 1]);
        a2 += a * __ldg(&hw3[src * 3 + 2]);
    }
    out[dst * 3 + 0] = a0 + b3[0] + res[dst * 3 + 0];
    out[dst * 3 + 1] = a1 + b3[1] + res[dst * 3 + 1];
    out[dst * 3 + 2] = a2 + b3[2] + res[dst * 3 + 2];
}

// ---------------- input residual ----------------
__global__ void resid_kernel(const float* __restrict__ x, const float* __restrict__ rw,
                             const float* __restrict__ rb, float* res) {
    int n = blockIdx.x, t = threadIdx.x;
    float a = x[(size_t)n * 128 + t];
    float p0 = a * rw[t], p1 = a * rw[128 + t], p2 = a * rw[256 + t];
    __shared__ float sh[3][4];
    for (int o = 16; o > 0; o >>= 1) {
        p0 += __shfl_down_sync(0xffffffffu, p0, o);
        p1 += __shfl_down_sync(0xffffffffu, p1, o);
        p2 += __shfl_down_sync(0xffffffffu, p2, o);
    }
    int w = t >> 5, l = t & 31;
    if (l == 0) { sh[0][w] = p0; sh[1][w] = p1; sh[2][w] = p2; }
    __syncthreads();
    if (t == 0) {
        res[n * 3 + 0] = sh[0][0] + sh[0][1] + sh[0][2] + sh[0][3] + rb[0];
        res[n * 3 + 1] = sh[1][0] + sh[1][1] + sh[1][2] + sh[1][3] + rb[1];
        res[n * 3 + 2] = sh[2][0] + sh[2][1] + sh[2][2] + sh[2][3] + rb[2];
    }
}

// ---------------- launch ----------------
extern "C" void kernel_launch(void* const* d_in, const int* in_sizes, int n_in,
                              void* d_out, int out_size) {
    const float* x    = (const float*)d_in[0];
    const int*   ei   = (const int*)d_in[1];
    const float* resW = (const float*)d_in[2];
    const float* resb = (const float*)d_in[3];

    const float* lng[4];  const float* lnb[4];
    const float* Wl[4];   const float* asr[4];
    const float* adt[4];  const float* bl[4];
    for (int l = 0; l < 4; l++) {
        int base = 4 + 6 * l;
        lng[l] = (const float*)d_in[base + 0];
        lnb[l] = (const float*)d_in[base + 1];
        Wl[l]  = (const float*)d_in[base + 2];
        asr[l] = (const float*)d_in[base + 3];
        adt[l] = (const float*)d_in[base + 4];
        bl[l]  = (const float*)d_in[base + 5];
    }

    float *ln_, *hw_, *h_, *alsrc_, *aldst_, *sinv_, *alpha_, *res_;
    int *deg_, *rp_, *cur_, *csrc_;
    cudaGetSymbolAddress((void**)&ln_,    g_ln);
    cudaGetSymbolAddress((void**)&hw_,    g_hw);
    cudaGetSymbolAddress((void**)&h_,     g_h);
    cudaGetSymbolAddress((void**)&alsrc_, g_alsrc);
    cudaGetSymbolAddress((void**)&aldst_, g_aldst);
    cudaGetSymbolAddress((void**)&sinv_,  g_sinv);
    cudaGetSymbolAddress((void**)&alpha_, g_alpha);
    cudaGetSymbolAddress((void**)&res_,   g_res);
    cudaGetSymbolAddress((void**)&deg_,   g_deg);
    cudaGetSymbolAddress((void**)&rp_,    g_rowptr);
    cudaGetSymbolAddress((void**)&cur_,   g_cursor);
    cudaGetSymbolAddress((void**)&csrc_,  g_csrc);

    zero_deg_kernel<<<(NN + 255) / 256, 256>>>(deg_);
    deg_kernel<<<(EP + 255) / 256, 256>>>(ei, deg_);
    scan_kernel<<<1, 1024>>>(deg_, rp_, cur_);
    scatter_kernel<<<(EP + 255) / 256, 256>>>(ei, cur_, csrc_);

    resid_kernel<<<NN, 128>>>(x, resW, resb, res_);
    ln_kernel<<<NN, 128>>>(x, lng[0], lnb[0], ln_, CIN);

    for (int l = 0; l < 3; l++) {
        int ci = (l == 0) ? CIN : HC;
        gemm_tf32<<<dim3(HC / BN, NP / BM), 256>>>(ln_, Wl[l], hw_, NN, ci, HC);
        attn_kernel<<<NN, 256>>>(hw_, asr[l], adt[l], alsrc_, aldst_);
        soft8_kernel<<<(NN * HEADS + 255) / 256, 256>>>(rp_, csrc_, alsrc_, aldst_, alpha_, sinv_);
        msgB_kernel<<<NN, 128>>>(rp_, csrc_, alpha_, sinv_, hw_, bl[l],
                                 lng[l + 1], lnb[l + 1], h_, ln_, l > 0 ? 1 : 0);
    }

    gemm3_kernel<<<NN, 128>>>(ln_, Wl[3], asr[3], adt[3], hw_, alsrc_, aldst_);
    soft1_kernel<<<(NN + 255) / 256, 256>>>(rp_, csrc_, alsrc_, aldst_, alpha_, sinv_);
    final_gather<<<(NN + 255) / 256, 256>>>(rp_, csrc_, alpha_, sinv_, hw_, bl[3], res_, (float*)d_out);
}